// round 1
// baseline (speedup 1.0000x reference)
#include <cuda_runtime.h>
#include <stdint.h>

// Problem shapes (fixed by the dataset)
#define M_ROWS   2048
#define N_POOL   4096
#define K_DIM    768
#define EP_LEN   8
#define XB_ELEMS 309854208   // 2048*197*768
#define EKV_ELEMS 6291456    // 2048*4*768

// GEMM tiling
#define BM 128
#define BN 128
#define BK 16
#define SN 256                       // N columns handled per gemm block
#define GEMM_BLOCKS ((M_ROWS/BM)*(N_POOL/SN))   // 16*16 = 256
#define COPY_BLOCKS 512
#define TOTAL_BLOCKS (GEMM_BLOCKS + COPY_BLOCKS)

// Global scratch (no allocations allowed)
__device__ unsigned long long g_key[M_ROWS];
__device__ float g_rinv[N_POOL];

// XOR swizzle at float4-group granularity: spreads the strided float4 reads
// across all 8 bank-groups (2-cycle wavefronts instead of 4-way conflicts).
__device__ __forceinline__ int swz(int c) {
    int g = c >> 2;
    g ^= (g >> 3);
    return (g << 2) | (c & 3);
}

// ---------------------------------------------------------------------------
// Kernel 1: rinv[k] = 1/max(||e_k[k]||, eps), and init g_key to 0.
// One warp per e_k row. 512 blocks x 256 threads = 4096 warps.
// ---------------------------------------------------------------------------
__global__ void prep_kernel(const float* __restrict__ ek) {
    int gtid = blockIdx.x * blockDim.x + threadIdx.x;
    if (gtid < M_ROWS) g_key[gtid] = 0ull;

    int warp = gtid >> 5;
    int lane = threadIdx.x & 31;
    if (warp < N_POOL) {
        const float4* row = (const float4*)(ek + (size_t)warp * K_DIM);
        float s = 0.f;
        #pragma unroll
        for (int i = 0; i < 6; i++) {             // 6*32*4 = 768
            float4 v = row[lane + i * 32];
            s += v.x*v.x + v.y*v.y + v.z*v.z + v.w*v.w;
        }
        #pragma unroll
        for (int o = 16; o; o >>= 1) s += __shfl_xor_sync(0xffffffffu, s, o);
        if (lane == 0) g_rinv[warp] = 1.0f / fmaxf(sqrtf(s), 1e-12f);
    }
}

// ---------------------------------------------------------------------------
// Kernel 2 (fused): GEMM+argmax blocks and x_block copy blocks in one grid so
// the FMA-bound GEMM overlaps the DRAM-bound copy. Block IDs interleaved so
// wave-1 residency is ~half gemm / half copy.
// ---------------------------------------------------------------------------
__global__ void __launch_bounds__(256, 2)
main_kernel(const float* __restrict__ xq, const float* __restrict__ ek,
            const float* __restrict__ xb, float* __restrict__ out)
{
    int bid = blockIdx.x;
    bool is_gemm;
    int wid;
    if (bid < 2 * GEMM_BLOCKS) { is_gemm = ((bid & 1) == 0); wid = bid >> 1; }
    else                       { is_gemm = false; wid = GEMM_BLOCKS + (bid - 2 * GEMM_BLOCKS); }

    if (!is_gemm) {
        // ---- pass-through copy of x_block into out[2*EKV_ELEMS ...] ----
        const float4* src = (const float4*)xb;
        float4* dst = (float4*)(out + 2 * (size_t)EKV_ELEMS);
        const long long n4 = XB_ELEMS / 4;                  // 77463552
        const long long stride = (long long)COPY_BLOCKS * 256;
        for (long long i = (long long)wid * 256 + threadIdx.x; i < n4; i += stride)
            dst[i] = src[i];
        return;
    }

    // ---- fp32 GEMM + running argmax over this block's N-slice ----
    __shared__ float As[BK][BM];
    __shared__ float Bs[BK][BN];

    const int m_tile  = wid & 15;
    const int n_slice = wid >> 4;
    const int m_base  = m_tile * BM;

    const int t   = threadIdx.x;
    const int lm  = t & 127;             // row within tile for gmem loads
    const int j0  = (t >> 7) << 3;       // k-subrange (0 or 8) this thread loads
    const int r0  = (t >> 4) << 3;       // microtile row origin
    const int c0  = (t & 15) << 3;       // microtile col origin
    const int swlm  = swz(lm);
    const int swr0  = swz(r0),  swr4 = swz(r0 + 4);
    const int swc0  = swz(c0),  swc4 = swz(c0 + 4);

    float    bestv[8];
    unsigned bestn[8];
    #pragma unroll
    for (int i = 0; i < 8; i++) { bestv[i] = -1e30f; bestn[i] = 0u; }

    const float* arow = xq + (size_t)(m_base + lm) * K_DIM + j0;

    for (int nc = 0; nc < SN; nc += BN) {
        const int n_base = n_slice * SN + nc;
        const float* brow = ek + (size_t)(n_base + lm) * K_DIM + j0;

        float acc[8][8];
        #pragma unroll
        for (int i = 0; i < 8; i++)
            #pragma unroll
            for (int j = 0; j < 8; j++) acc[i][j] = 0.f;

        for (int k0 = 0; k0 < K_DIM; k0 += BK) {
            float4 a0 = *(const float4*)(arow + k0);
            float4 a1 = *(const float4*)(arow + k0 + 4);
            float4 b0 = *(const float4*)(brow + k0);
            float4 b1 = *(const float4*)(brow + k0 + 4);
            __syncthreads();   // previous iter's smem reads done before overwrite
            As[j0+0][swlm] = a0.x; As[j0+1][swlm] = a0.y;
            As[j0+2][swlm] = a0.z; As[j0+3][swlm] = a0.w;
            As[j0+4][swlm] = a1.x; As[j0+5][swlm] = a1.y;
            As[j0+6][swlm] = a1.z; As[j0+7][swlm] = a1.w;
            Bs[j0+0][swlm] = b0.x; Bs[j0+1][swlm] = b0.y;
            Bs[j0+2][swlm] = b0.z; Bs[j0+3][swlm] = b0.w;
            Bs[j0+4][swlm] = b1.x; Bs[j0+5][swlm] = b1.y;
            Bs[j0+6][swlm] = b1.z; Bs[j0+7][swlm] = b1.w;
            __syncthreads();

            #pragma unroll
            for (int kk = 0; kk < BK; kk++) {
                float4 av0 = *(const float4*)&As[kk][swr0];
                float4 av1 = *(const float4*)&As[kk][swr4];
                float4 bv0 = *(const float4*)&Bs[kk][swc0];
                float4 bv1 = *(const float4*)&Bs[kk][swc4];
                float a[8] = {av0.x, av0.y, av0.z, av0.w, av1.x, av1.y, av1.z, av1.w};
                float b[8] = {bv0.x, bv0.y, bv0.z, bv0.w, bv1.x, bv1.y, bv1.z, bv1.w};
                #pragma unroll
                for (int i = 0; i < 8; i++)
                    #pragma unroll
                    for (int j = 0; j < 8; j++)
                        acc[i][j] = fmaf(a[i], b[j], acc[i][j]);
            }
        }

        // epilogue: scale by 1/||e_k||, update per-thread running best
        #pragma unroll
        for (int j = 0; j < 8; j++) {
            const int n = n_base + c0 + j;
            const float rv = g_rinv[n];
            #pragma unroll
            for (int i = 0; i < 8; i++) {
                float s = acc[i][j] * rv;
                if (s > bestv[i]) { bestv[i] = s; bestn[i] = (unsigned)n; }
            }
        }
    }

    // Merge across the 16 threads that share rows r0..r0+7 (contiguous lanes),
    // then atomicMax into the global per-row key.
    #pragma unroll
    for (int i = 0; i < 8; i++) {
        unsigned u = __float_as_uint(bestv[i]);
        u = (u & 0x80000000u) ? ~u : (u | 0x80000000u);   // order-monotonic encode
        unsigned long long key =
            ((unsigned long long)u << 32) | (unsigned long long)(0xFFFFFFFFu - bestn[i]);
        #pragma unroll
        for (int o = 8; o; o >>= 1) {
            unsigned long long other = __shfl_xor_sync(0xffffffffu, key, o);
            if (other > key) key = other;
        }
        if ((t & 15) == 0)
            atomicMax(&g_key[m_base + r0 + i], key);
    }
}

// ---------------------------------------------------------------------------
// Kernel 3: gather e_p[idx] -> Ek (rows 0..3) and Ev (rows 4..7).
// One block per query row, float4 copies.
// ---------------------------------------------------------------------------
__global__ void gather_kernel(const float* __restrict__ ep, float* __restrict__ out) {
    const int b = blockIdx.x;
    const unsigned idx = 0xFFFFFFFFu - (unsigned)(g_key[b] & 0xFFFFFFFFull);
    const float4* src = (const float4*)(ep + (size_t)idx * (EP_LEN * K_DIM));
    float4* dEk = (float4*)out + (size_t)b * (4 * K_DIM / 4);
    float4* dEv = (float4*)(out + (size_t)EKV_ELEMS) + (size_t)b * (4 * K_DIM / 4);
    for (int j = threadIdx.x; j < (EP_LEN * K_DIM) / 4; j += blockDim.x) {   // 1536
        float4 v = src[j];
        if (j < 768) dEk[j] = v;
        else         dEv[j - 768] = v;
    }
}

// ---------------------------------------------------------------------------
extern "C" void kernel_launch(void* const* d_in, const int* in_sizes, int n_in,
                              void* d_out, int out_size)
{
    const float *xq = nullptr, *xb = nullptr, *ek = nullptr, *ep = nullptr;
    for (int i = 0; i < n_in; i++) {
        long long sz = in_sizes[i];
        if      (sz == (long long)M_ROWS * K_DIM)          xq = (const float*)d_in[i];
        else if (sz == (long long)XB_ELEMS)                xb = (const float*)d_in[i];
        else if (sz == (long long)N_POOL * K_DIM)          ek = (const float*)d_in[i];
        else if (sz == (long long)N_POOL * EP_LEN * K_DIM) ep = (const float*)d_in[i];
        // l (size 1) intentionally ignored: e_p.shape[1]//2 == 4 regardless
    }
    float* out = (float*)d_out;

    prep_kernel<<<512, 256>>>(ek);
    main_kernel<<<TOTAL_BLOCKS, 256>>>(xq, ek, xb, out);
    gather_kernel<<<M_ROWS, 256>>>(ep, out);
}

// round 2
// speedup vs baseline: 1.1434x; 1.1434x over previous
#include <cuda_runtime.h>
#include <cuda_bf16.h>
#include <stdint.h>

// Fixed problem shapes
#define M_ROWS   2048
#define N_POOL   4096
#define K_DIM    768
#define EP_LEN   8
#define XB_ELEMS 309854208LL   // 2048*197*768
#define EKV_ELEMS 6291456LL    // 2048*4*768

// GEMM tiling (tensor-core bf16)
#define GBM 128
#define GBN 128
#define GBK 64
#define GEMM_BLOCKS ((M_ROWS/GBM)*(N_POOL/GBN))   // 16*32 = 512
#define COPY_BLOCKS 1024
#define CPY_UNROLL 8
#define TAU 0.01f              // > 2x worst-case bf16 score error (~0.0082)

// Device-global scratch (static allocation — allowed)
__device__ float g_rinv[N_POOL];
__device__ __align__(16) __nv_bfloat16 g_nkbf[N_POOL * K_DIM];   // normalized e_k, bf16
__device__ __align__(16) __nv_bfloat16 g_qbf[M_ROWS * K_DIM];    // normalized q, bf16
__device__ float g_scores[(size_t)M_ROWS * N_POOL];              // approx cos sims

// ---------------------------------------------------------------------------
// Kernel 1: normalize e_k and x_querry, convert to bf16; store 1/||e_k||.
// One warp per row. 6144 rows total -> 768 blocks x 256 threads.
// ---------------------------------------------------------------------------
__global__ void prep_kernel(const float* __restrict__ xq, const float* __restrict__ ek)
{
    int warp = (blockIdx.x * blockDim.x + threadIdx.x) >> 5;
    int lane = threadIdx.x & 31;

    const float* src;
    __nv_bfloat16* dst;
    int row;
    bool is_ek = (warp < N_POOL);
    if (is_ek) {
        row = warp;
        src = ek + (size_t)row * K_DIM;
        dst = g_nkbf + (size_t)row * K_DIM;
    } else {
        row = warp - N_POOL;
        if (row >= M_ROWS) return;
        src = xq + (size_t)row * K_DIM;
        dst = g_qbf + (size_t)row * K_DIM;
    }

    float4 v[6];
    float s = 0.f;
    #pragma unroll
    for (int i = 0; i < 6; i++) {            // 6*32*4 = 768
        v[i] = ((const float4*)src)[lane + i * 32];
        s += v[i].x*v[i].x + v[i].y*v[i].y + v[i].z*v[i].z + v[i].w*v[i].w;
    }
    #pragma unroll
    for (int o = 16; o; o >>= 1) s += __shfl_xor_sync(0xffffffffu, s, o);
    float rinv = 1.0f / fmaxf(sqrtf(s), 1e-12f);
    if (is_ek && lane == 0) g_rinv[row] = rinv;

    #pragma unroll
    for (int i = 0; i < 6; i++) {
        __nv_bfloat162 lo = __floats2bfloat162_rn(v[i].x * rinv, v[i].y * rinv);
        __nv_bfloat162 hi = __floats2bfloat162_rn(v[i].z * rinv, v[i].w * rinv);
        uint2 u;
        u.x = *(unsigned*)&lo;
        u.y = *(unsigned*)&hi;
        ((uint2*)dst)[lane + i * 32] = u;
    }
}

// ---------------------------------------------------------------------------
// Kernel 2 (fused): bf16 tensor-core GEMM blocks (write approx score matrix)
// interleaved with high-MLP streaming copy blocks (x_block pass-through).
// ---------------------------------------------------------------------------
__global__ void __launch_bounds__(256, 2)
main_kernel(const float* __restrict__ xb, float* __restrict__ out)
{
    const int bid = blockIdx.x;
    int role, wid;  // role 0 = gemm, 1 = copy
    if (bid < 2 * GEMM_BLOCKS) { role = bid & 1; wid = bid >> 1; }
    else                       { role = 1; wid = GEMM_BLOCKS + (bid - 2 * GEMM_BLOCKS); }

    if (role) {
        // ---- streaming copy, 8 independent loads in flight per thread ----
        const float4* __restrict__ src = (const float4*)xb;
        float4* __restrict__ dst = (float4*)(out + 2 * EKV_ELEMS);
        const long long n4 = XB_ELEMS / 4;                    // 77463552
        const long long SPAN = (long long)COPY_BLOCKS * 256;  // 262144
        long long base = (long long)wid * 256 + threadIdx.x;
        for (long long i0 = base; i0 < n4; i0 += SPAN * CPY_UNROLL) {
            float4 v[CPY_UNROLL];
            #pragma unroll
            for (int j = 0; j < CPY_UNROLL; j++) {
                long long idx = i0 + (long long)j * SPAN;
                if (idx < n4) v[j] = __ldcs(&src[idx]);
            }
            #pragma unroll
            for (int j = 0; j < CPY_UNROLL; j++) {
                long long idx = i0 + (long long)j * SPAN;
                if (idx < n4) __stcs(&dst[idx], v[j]);
            }
        }
        return;
    }

    // ---- bf16 mma.sync GEMM: 128x128 tile, 8 warps (4x2), warp = 32x64 ----
    __shared__ __align__(16) __nv_bfloat16 As[GBM * GBK];
    __shared__ __align__(16) __nv_bfloat16 Bs[GBN * GBK];
    uint4* As4 = (uint4*)As;
    uint4* Bs4 = (uint4*)Bs;

    const int m_base = (wid & 15) * GBM;
    const int n_base = (wid >> 4) * GBN;
    const int t = threadIdx.x;
    const int warp = t >> 5, lane = t & 31;
    const int wm = warp >> 1, wn = warp & 1;

    const uint4* __restrict__ gA = (const uint4*)g_qbf;   // row stride 96 uint4
    const uint4* __restrict__ gB = (const uint4*)g_nkbf;

    uint32_t asbase = (uint32_t)__cvta_generic_to_shared(As);
    uint32_t bsbase = (uint32_t)__cvta_generic_to_shared(Bs);

    float d[2][8][4];
    #pragma unroll
    for (int i = 0; i < 2; i++)
        #pragma unroll
        for (int j = 0; j < 8; j++)
            #pragma unroll
            for (int q = 0; q < 4; q++) d[i][j][q] = 0.f;

    for (int k0 = 0; k0 < K_DIM; k0 += GBK) {
        uint4 va[4], vb[4];
        #pragma unroll
        for (int p = 0; p < 4; p++) {
            int id = p * 256 + t;          // 0..1023 chunks of 16B
            int row = id >> 3, ch = id & 7;
            va[p] = gA[(size_t)(m_base + row) * 96 + (k0 >> 3) + ch];
            vb[p] = gB[(size_t)(n_base + row) * 96 + (k0 >> 3) + ch];
        }
        __syncthreads();
        #pragma unroll
        for (int p = 0; p < 4; p++) {
            int id = p * 256 + t;
            int row = id >> 3, ch = id & 7;
            As4[row * 8 + (ch ^ (row & 7))] = va[p];
            Bs4[row * 8 + (ch ^ (row & 7))] = vb[p];
        }
        __syncthreads();

        #pragma unroll
        for (int ks = 0; ks < 4; ks++) {
            uint32_t a[2][4];
            #pragma unroll
            for (int i = 0; i < 2; i++) {
                int row = wm * 32 + i * 16 + (lane & 15);
                int ch = (ks * 2 + (lane >> 4)) ^ (row & 7);
                uint32_t addr = asbase + row * 128 + (ch << 4);
                asm volatile("ldmatrix.sync.aligned.m8n8.x4.shared.b16 {%0,%1,%2,%3}, [%4];"
                    : "=r"(a[i][0]), "=r"(a[i][1]), "=r"(a[i][2]), "=r"(a[i][3])
                    : "r"(addr));
            }
            uint32_t b[8][2];
            #pragma unroll
            for (int jp = 0; jp < 4; jp++) {
                int row = wn * 64 + jp * 16 + ((lane >> 4) << 3) + (lane & 7);
                int ch = (ks * 2 + ((lane >> 3) & 1)) ^ (row & 7);
                uint32_t addr = bsbase + row * 128 + (ch << 4);
                asm volatile("ldmatrix.sync.aligned.m8n8.x4.shared.b16 {%0,%1,%2,%3}, [%4];"
                    : "=r"(b[2*jp][0]), "=r"(b[2*jp][1]), "=r"(b[2*jp+1][0]), "=r"(b[2*jp+1][1])
                    : "r"(addr));
            }
            #pragma unroll
            for (int i = 0; i < 2; i++)
                #pragma unroll
                for (int j = 0; j < 8; j++)
                    asm volatile("mma.sync.aligned.m16n8k16.row.col.f32.bf16.bf16.f32 "
                        "{%0,%1,%2,%3}, {%4,%5,%6,%7}, {%8,%9}, {%0,%1,%2,%3};"
                        : "+f"(d[i][j][0]), "+f"(d[i][j][1]), "+f"(d[i][j][2]), "+f"(d[i][j][3])
                        : "r"(a[i][0]), "r"(a[i][1]), "r"(a[i][2]), "r"(a[i][3]),
                          "r"(b[j][0]), "r"(b[j][1]));
        }
    }

    // epilogue: write approx scores
    #pragma unroll
    for (int i = 0; i < 2; i++) {
        int gm = m_base + wm * 32 + i * 16 + (lane >> 2);
        #pragma unroll
        for (int j = 0; j < 8; j++) {
            int gn = n_base + wn * 64 + j * 8 + (lane & 3) * 2;
            *(float2*)&g_scores[(size_t)gm * N_POOL + gn] = make_float2(d[i][j][0], d[i][j][1]);
            *(float2*)&g_scores[(size_t)(gm + 8) * N_POOL + gn] = make_float2(d[i][j][2], d[i][j][3]);
        }
    }
}

// ---------------------------------------------------------------------------
// Kernel 3: per query row — approx max, fp32 rescore of near-max candidates,
// exact argmax with first-index tie-break, then gather e_p[idx] -> Ek/Ev.
// One block per row.
// ---------------------------------------------------------------------------
__global__ void __launch_bounds__(256)
rescore_gather_kernel(const float* __restrict__ xq, const float* __restrict__ ek,
                      const float* __restrict__ ep, float* __restrict__ out)
{
    const int b = blockIdx.x;
    const int t = threadIdx.x;
    const float* __restrict__ srow = g_scores + (size_t)b * N_POOL;

    __shared__ float smax[8];
    __shared__ unsigned long long sbest;

    float sv[16];
    float lm = -1e30f;
    #pragma unroll
    for (int i = 0; i < 16; i++) {
        sv[i] = srow[t + i * 256];
        lm = fmaxf(lm, sv[i]);
    }
    #pragma unroll
    for (int o = 16; o; o >>= 1) lm = fmaxf(lm, __shfl_xor_sync(0xffffffffu, lm, o));
    if ((t & 31) == 0) smax[t >> 5] = lm;
    if (t == 0) sbest = 0ull;
    __syncthreads();

    float rowmax = smax[0];
    #pragma unroll
    for (int w = 1; w < 8; w++) rowmax = fmaxf(rowmax, smax[w]);
    const float thresh = rowmax - TAU;

    const float4* __restrict__ qr = (const float4*)(xq + (size_t)b * K_DIM);

    #pragma unroll
    for (int i = 0; i < 16; i++) {
        if (sv[i] >= thresh) {
            int n = t + i * 256;
            const float4* __restrict__ er = (const float4*)(ek + (size_t)n * K_DIM);
            float a0 = 0.f, a1 = 0.f, a2 = 0.f, a3 = 0.f;
            for (int k = 0; k < 192; k += 4) {
                float4 e0 = er[k],     q0 = qr[k];
                float4 e1 = er[k + 1], q1 = qr[k + 1];
                float4 e2 = er[k + 2], q2 = qr[k + 2];
                float4 e3 = er[k + 3], q3 = qr[k + 3];
                a0 += e0.x*q0.x + e0.y*q0.y + e0.z*q0.z + e0.w*q0.w;
                a1 += e1.x*q1.x + e1.y*q1.y + e1.z*q1.z + e1.w*q1.w;
                a2 += e2.x*q2.x + e2.y*q2.y + e2.z*q2.z + e2.w*q2.w;
                a3 += e3.x*q3.x + e3.y*q3.y + e3.z*q3.z + e3.w*q3.w;
            }
            float val = (a0 + a1 + a2 + a3) * g_rinv[n];
            unsigned u = __float_as_uint(val);
            u = (u & 0x80000000u) ? ~u : (u | 0x80000000u);   // order-monotonic
            unsigned long long key =
                ((unsigned long long)u << 32) | (unsigned long long)(0xFFFFFFFFu - (unsigned)n);
            atomicMax(&sbest, key);
        }
    }
    __syncthreads();

    const unsigned idx = 0xFFFFFFFFu - (unsigned)(sbest & 0xFFFFFFFFull);

    // gather e_p[idx]: rows 0..3 -> Ek, rows 4..7 -> Ev
    const float4* __restrict__ src = (const float4*)(ep + (size_t)idx * (EP_LEN * K_DIM));
    float4* dEk = (float4*)out + (size_t)b * (4 * K_DIM / 4);
    float4* dEv = (float4*)(out + EKV_ELEMS) + (size_t)b * (4 * K_DIM / 4);
    #pragma unroll
    for (int j = t; j < 768; j += 256) dEk[j] = src[j];
    #pragma unroll
    for (int j = t; j < 768; j += 256) dEv[j] = src[768 + j];
}

// ---------------------------------------------------------------------------
extern "C" void kernel_launch(void* const* d_in, const int* in_sizes, int n_in,
                              void* d_out, int out_size)
{
    const float *xq = nullptr, *xb = nullptr, *ek = nullptr, *ep = nullptr;
    for (int i = 0; i < n_in; i++) {
        long long sz = in_sizes[i];
        if      (sz == (long long)M_ROWS * K_DIM)          xq = (const float*)d_in[i];
        else if (sz == XB_ELEMS)                           xb = (const float*)d_in[i];
        else if (sz == (long long)N_POOL * K_DIM)          ek = (const float*)d_in[i];
        else if (sz == (long long)N_POOL * EP_LEN * K_DIM) ep = (const float*)d_in[i];
        // 'l' (size 1) ignored: e_p.shape[1]//2 == 4 regardless of l in {3,4,5}
    }
    float* out = (float*)d_out;

    prep_kernel<<<768, 256>>>(xq, ek);
    main_kernel<<<2 * GEMM_BLOCKS + (COPY_BLOCKS - GEMM_BLOCKS), 256>>>(xb, out);
    rescore_gather_kernel<<<M_ROWS, 256>>>(xq, ek, ep, out);
}